// round 15
// baseline (speedup 1.0000x reference)
#include <cuda_runtime.h>
#include <cuda_fp16.h>
#include <cstdint>

#define BATCH 256
#define ENC_DIM 256
#define HEAD_HID 128

// ---------------------------------------------------------------------------
// Scratch (static __device__ — no allocations allowed)
// ---------------------------------------------------------------------------
__device__ __half g_imgT[(size_t)BATCH * 130 * 130 * 4];        // padded NHWC4
__device__ __half g_act1[(size_t)BATCH * 64 * 64 * 64];         // conv1 out NHWC
__device__ __half g_act2[(size_t)BATCH * 32 * 32 * 128];        // conv2 out NHWC
__device__ __half g_w1rep[64 * 64];
__device__ __half g_w2rep[128 * 576];
__device__ __half g_w3rep[256 * 1152];
__device__ float  g_vpart[(size_t)BATCH * 2 * 256];

// ---------------------------------------------------------------------------
// helpers
// ---------------------------------------------------------------------------
__device__ __forceinline__ uint32_t smem_u32(const void* p) {
    uint32_t a;
    asm("{ .reg .u64 t; cvta.to.shared.u64 t, %1; cvt.u32.u64 %0, t; }"
        : "=r"(a) : "l"(p));
    return a;
}
__device__ __forceinline__ uint32_t swz(uint32_t off) {
    return off ^ ((off >> 3) & 0x70);
}
__device__ __forceinline__ void ldm_x4(uint32_t r[4], uint32_t addr) {
    asm volatile("ldmatrix.sync.aligned.m8n8.x4.shared.b16 {%0,%1,%2,%3}, [%4];"
                 : "=r"(r[0]), "=r"(r[1]), "=r"(r[2]), "=r"(r[3]) : "r"(addr));
}
__device__ __forceinline__ void mma_f16(float c[4], const uint32_t a[4],
                                        uint32_t b0, uint32_t b1) {
    asm volatile(
        "mma.sync.aligned.m16n8k16.row.col.f32.f16.f16.f32 "
        "{%0,%1,%2,%3},{%4,%5,%6,%7},{%8,%9},{%0,%1,%2,%3};"
        : "+f"(c[0]), "+f"(c[1]), "+f"(c[2]), "+f"(c[3])
        : "r"(a[0]), "r"(a[1]), "r"(a[2]), "r"(a[3]), "r"(b0), "r"(b1));
}
#define CP_COMMIT() asm volatile("cp.async.commit_group;" ::: "memory")
#define CP_WAIT0()  asm volatile("cp.async.wait_group 0;" ::: "memory")
#define CP_WAIT1()  asm volatile("cp.async.wait_group 1;" ::: "memory")

// ---------------------------------------------------------------------------
// Fused repack kernel (one launch): img -> padded NHWC4 half, weights -> K-major
// ---------------------------------------------------------------------------
#define IMG_ELEMS (BATCH * 130 * 130)        // 4326400
#define W_ELEMS   (4096 + 73728 + 294912)    // 372736

__device__ __forceinline__ void repack_one(const float* __restrict__ src,
                                           __half* __restrict__ dst,
                                           int idx, int IC, int ICP, int K)
{
    int oc = idx / K;
    int k = idx - oc * K;
    int tap = k / ICP;
    int ic = k - tap * ICP;
    float v = (tap < 9 && ic < IC) ? src[(oc * IC + ic) * 9 + tap] : 0.f;
    dst[idx] = __float2half_rn(v);
}

__global__ void repack_all(const float* __restrict__ img, __half* __restrict__ dimg,
                           const float* __restrict__ c1w, const float* __restrict__ c2w,
                           const float* __restrict__ c3w,
                           __half* __restrict__ w1, __half* __restrict__ w2,
                           __half* __restrict__ w3)
{
    int idx = blockIdx.x * 512 + threadIdx.x;
    if (idx < IMG_ELEMS) {
        int n = idx / 16900;
        int r = idx - n * 16900;
        int ihp = r / 130;
        int iwp = r - ihp * 130;
        int ih = ihp - 1, iw = iwp - 1;
        float c0 = 0.f, c1 = 0.f, c2 = 0.f;
        if ((unsigned)ih < 128u && (unsigned)iw < 128u) {
            size_t b = (size_t)n * 3 * 16384 + ih * 128 + iw;
            c0 = img[b]; c1 = img[b + 16384]; c2 = img[b + 32768];
        }
        __half2 lo = __floats2half2_rn(c0, c1);
        __half2 hi = __floats2half2_rn(c2, 0.f);
        uint2 v;
        v.x = *(uint32_t*)&lo;
        v.y = *(uint32_t*)&hi;
        *(uint2*)(dimg + (size_t)idx * 4) = v;
    } else {
        int w = idx - IMG_ELEMS;
        if (w < 4096) repack_one(c1w, w1, w, 3, 4, 64);
        else if (w < 4096 + 73728) repack_one(c2w, w2, w - 4096, 64, 64, 576);
        else if (w < W_ELEMS) repack_one(c3w, w3, w - 4096 - 73728, 128, 128, 1152);
    }
}

// ---------------------------------------------------------------------------
// conv1 kernel: 256 threads, NB=64, NCH=1, 3 CTA/SM, KSTEPS=3 (K 36->48).
// Padding bytes 72..95 of each A row (beyond the 9 taps, within the 3 K-steps
// read range) are zeroed precisely; taps write 0..71, so no overlap/race.
// ---------------------------------------------------------------------------
__global__ void __launch_bounds__(256, 3)
conv1_kernel(const __half* __restrict__ in, const __half* __restrict__ wrep,
             const float* __restrict__ bias, __half* __restrict__ outp)
{
    constexpr int OW = 64, OH = 64;
    constexpr int NB = 64;
    constexpr uint32_t OFFA = 1024;
    constexpr uint32_t OFFB = OFFA + 16384;

    extern __shared__ char smem[];
    const uint32_t sb = smem_u32(smem);
    float* s_bias = (float*)smem;

    const int bid = blockIdx.x;
    const int n = bid >> 5;
    const int mblk = bid & 31;
    const int oh0 = mblk * 2;

    const int tid = threadIdx.x;
    const int warp = tid >> 5;
    const int lane = tid & 31;
    const int mwarp = warp >> 1;
    const int nwarp = warp & 1;

    if (tid < NB) s_bias[tid] = bias[tid];

    // precise zero of padding bytes 72..95 per row (rows 0..127)
    if (tid < 128) {
        const uint32_t rb = OFFA + (uint32_t)tid * 128;
        *(uint64_t*)(smem + swz(rb + 72)) = 0ull;
        *(uint64_t*)(smem + swz(rb + 80)) = 0ull;
        *(uint64_t*)(smem + swz(rb + 88)) = 0ull;
    }

    {
        const int am = tid >> 1;
        const int a_ohl = am >> 6;
        const int a_ow = am & 63;
        const int ihb = (oh0 + a_ohl) * 2;
        const int iwb = a_ow * 2;
#pragma unroll
        for (int i = 0; i < 5; i++) {
            int j = (tid & 1) + 2 * i;
            if (j <= 8) {
                int kh = j / 3, kw = j - kh * 3;
                const __half* src = in + (((size_t)n * 130 + ihb + kh) * 130 + iwb + kw) * 4;
                uint32_t dst = sb + OFFA + swz((uint32_t)(am * 128 + j * 8));
                asm volatile("cp.async.ca.shared.global [%0], [%1], 8;"
                             :: "r"(dst), "l"(src));
            }
        }
        const int bn = tid >> 2;
        const int bseg = (tid & 3) * 2;
#pragma unroll
        for (int i = 0; i < 2; i++) {
            const __half* src = wrep + (size_t)bn * 64 + (bseg + i) * 8;
            uint32_t dst = sb + OFFB + swz((uint32_t)(bn * 128 + (bseg + i) * 16));
            asm volatile("cp.async.cg.shared.global [%0], [%1], 16;"
                         :: "r"(dst), "l"(src));
        }
    }
    CP_COMMIT();
    CP_WAIT0();
    __syncthreads();

    float acc[2][4][4];
#pragma unroll
    for (int mt = 0; mt < 2; mt++)
#pragma unroll
        for (int nt = 0; nt < 4; nt++)
#pragma unroll
            for (int i = 0; i < 4; i++) acc[mt][nt][i] = 0.f;

#pragma unroll
    for (int ks = 0; ks < 3; ks++) {   // K=36 padded to 48: 3 steps of 16
        const uint32_t colb = ks * 32 + ((lane >> 4) << 4);
        uint32_t a[2][4], bf[2][4];
#pragma unroll
        for (int mt = 0; mt < 2; mt++) {
            const uint32_t row = mwarp * 32 + mt * 16 + (lane & 15);
            ldm_x4(a[mt], sb + OFFA + swz(row * 128 + colb));
        }
#pragma unroll
        for (int np = 0; np < 2; np++) {
            const uint32_t row = nwarp * 32 + np * 16 + (lane & 15);
            ldm_x4(bf[np], sb + OFFB + swz(row * 128 + colb));
        }
#pragma unroll
        for (int mt = 0; mt < 2; mt++)
#pragma unroll
            for (int nt = 0; nt < 4; nt++)
                mma_f16(acc[mt][nt], a[mt], bf[nt >> 1][nt & 1],
                        bf[nt >> 1][2 + (nt & 1)]);
    }
    __syncthreads();

    constexpr uint32_t ES = NB * 2 + 16;
    char* epi = smem + OFFA;
#pragma unroll
    for (int mt = 0; mt < 2; mt++) {
        const int r0 = mwarp * 32 + mt * 16 + (lane >> 2);
#pragma unroll
        for (int nt = 0; nt < 4; nt++) {
            const int c0 = nwarp * 32 + nt * 8 + (lane & 3) * 2;
            const float b0 = s_bias[c0], b1 = s_bias[c0 + 1];
            __half2 v0 = __floats2half2_rn(fmaxf(acc[mt][nt][0] + b0, 0.f),
                                           fmaxf(acc[mt][nt][1] + b1, 0.f));
            __half2 v1 = __floats2half2_rn(fmaxf(acc[mt][nt][2] + b0, 0.f),
                                           fmaxf(acc[mt][nt][3] + b1, 0.f));
            *(__half2*)(epi + r0 * ES + c0 * 2) = v0;
            *(__half2*)(epi + (r0 + 8) * ES + c0 * 2) = v1;
        }
    }
    __syncthreads();
#pragma unroll
    for (int i = 0; i < 4; i++) {
        int idx = tid + i * 256;
        int r2 = idx >> 3;
        int j = idx & 7;
        uint4 v = *(const uint4*)(epi + r2 * ES + j * 16);
        int ohl = r2 >> 6, ow = r2 & 63;
        __half* dst = outp + (((size_t)n * OH + oh0 + ohl) * OW + ow) * 64 + j * 8;
        *(uint4*)dst = v;
    }
}

// ---------------------------------------------------------------------------
// R7-proven conv (conv2/conv3): 256 thr, 8 warps 4Mx2N, NB=128, 2 CTA/SM.
// 3-buffer cp.async pipeline, one sync per chunk, wait->sync->mma->issue.
// do_mma splits each ks into two half-groups (B-frags 16->8 live regs) to
// give ptxas scheduling slack at the 128-reg cap.
// ---------------------------------------------------------------------------
template <int ICP, int KTOT, int OCTOT, int IH, int IW, int OH_TILE, bool FUSE_POOL>
__global__ void __launch_bounds__(256, 2)
conv_r7_kernel(const __half* __restrict__ in, const __half* __restrict__ wrep,
               const float* __restrict__ bias, void* __restrict__ outp)
{
    constexpr int OH = IH / 2, OW = IW / 2;
    constexpr int LOG_OW = (OW == 64) ? 6 : (OW == 32) ? 5 : 4;
    constexpr int NB = 128;
    constexpr int NCH = KTOT / 64;
    constexpr int CPT = ICP / 64;
    constexpr int MBLK = OH / OH_TILE;
    constexpr int NBLK = OCTOT / NB;
    constexpr int NT = 8;                   // NB/16
    constexpr uint32_t OFFA = 1024;
    constexpr uint32_t ABUF = 16384;
    constexpr uint32_t OFFB = OFFA + 3 * ABUF;
    constexpr uint32_t BBUF = NB * 128;

    extern __shared__ char smem[];
    const uint32_t sb = smem_u32(smem);
    float* s_bias = (float*)smem;

    const int bid = blockIdx.x;
    const int n = bid / (MBLK * NBLK);
    const int r = bid - n * (MBLK * NBLK);
    const int mblk = r / NBLK;
    const int nblk = r - mblk * NBLK;
    const int oh0 = mblk * OH_TILE;

    const int tid = threadIdx.x;
    const int warp = tid >> 5;
    const int lane = tid & 31;
    const int mwarp = warp >> 1;
    const int nwarp = warp & 1;

    if (tid < NB) s_bias[tid] = bias[nblk * NB + tid];

    const int am = tid >> 1;
    const int a_ohl = am >> LOG_OW;
    const int a_ow = am & (OW - 1);

    auto issueA = [&](int c, uint32_t abase) {
        const int tap = c / CPT;
        const int ic0 = (c & (CPT - 1)) * 64;
        const int kh = tap / 3, kw = tap - kh * 3;
        const int ih = (oh0 + a_ohl) * 2 - 1 + kh;
        const int iw = a_ow * 2 - 1 + kw;
        const bool valid = ((unsigned)ih < (unsigned)IH) &&
                           ((unsigned)iw < (unsigned)IW);
        const __half* src = valid
            ? in + (((size_t)n * IH + ih) * IW + iw) * ICP + ic0 : in;
        const int sz = valid ? 16 : 0;
#pragma unroll
        for (int i = 0; i < 4; i++) {
            int u = (tid & 1) * 4 + i;
            uint32_t dst = sb + abase + swz((uint32_t)(am * 128 + u * 16));
            asm volatile("cp.async.cg.shared.global [%0], [%1], 16, %2;"
                         :: "r"(dst), "l"(src + u * 8), "r"(sz));
        }
    };
    auto issueB = [&](int c, uint32_t bbase) {
#pragma unroll
        for (int i = 0; i < 4; i++) {
            int u = tid * 4 + i;
            int row = u >> 3, j = u & 7;
            const __half* src = wrep + (size_t)(nblk * NB + row) * KTOT + c * 64 + j * 8;
            uint32_t dst = sb + bbase + swz((uint32_t)(row * 128 + j * 16));
            asm volatile("cp.async.cg.shared.global [%0], [%1], 16;"
                         :: "r"(dst), "l"(src));
        }
    };

    float acc[2][NT][4];
#pragma unroll
    for (int mt = 0; mt < 2; mt++)
#pragma unroll
        for (int nt = 0; nt < NT; nt++)
#pragma unroll
            for (int i = 0; i < 4; i++) acc[mt][nt][i] = 0.f;

    auto do_mma = [&](uint32_t abase, uint32_t bbase) {
#pragma unroll
        for (int ks = 0; ks < 4; ks++) {
            const uint32_t colb = ks * 32 + ((lane >> 4) << 4);
            uint32_t a[2][4];
#pragma unroll
            for (int mt = 0; mt < 2; mt++) {
                const uint32_t row = mwarp * 32 + mt * 16 + (lane & 15);
                ldm_x4(a[mt], sb + abase + swz(row * 128 + colb));
            }
            // two half-groups: only 2 B-frag ldm (8 regs) live at a time
#pragma unroll
            for (int g = 0; g < 2; g++) {
                uint32_t bf0[4], bf1[4];
                {
                    const uint32_t row0 = nwarp * (NB / 2) + (g * 2) * 16 + (lane & 15);
                    const uint32_t row1 = nwarp * (NB / 2) + (g * 2 + 1) * 16 + (lane & 15);
                    ldm_x4(bf0, sb + bbase + swz(row0 * 128 + colb));
                    ldm_x4(bf1, sb + bbase + swz(row1 * 128 + colb));
                }
#pragma unroll
                for (int mt = 0; mt < 2; mt++) {
                    mma_f16(acc[mt][g * 4 + 0], a[mt], bf0[0], bf0[2]);
                    mma_f16(acc[mt][g * 4 + 1], a[mt], bf0[1], bf0[3]);
                    mma_f16(acc[mt][g * 4 + 2], a[mt], bf1[0], bf1[2]);
                    mma_f16(acc[mt][g * 4 + 3], a[mt], bf1[1], bf1[3]);
                }
            }
        }
    };

    issueB(0, OFFB);
    issueA(0, OFFA);
    CP_COMMIT();
    issueB(1, OFFB + BBUF);
    issueA(1, OFFA + ABUF);
    CP_COMMIT();

    int bi = 0;
#pragma unroll 1
    for (int c = 0; c < NCH; c++) {
        if (c + 1 < NCH) { CP_WAIT1(); } else { CP_WAIT0(); }
        __syncthreads();
        do_mma(OFFA + (uint32_t)bi * ABUF, OFFB + (uint32_t)bi * BBUF);
        if (c + 2 < NCH) {
            int b2 = bi + 2; if (b2 >= 3) b2 -= 3;
            issueB(c + 2, OFFB + (uint32_t)b2 * BBUF);
            issueA(c + 2, OFFA + (uint32_t)b2 * ABUF);
            CP_COMMIT();
        }
        if (++bi == 3) bi = 0;
    }
    __syncthreads();

    if (!FUSE_POOL) {
        constexpr uint32_t ES = NB * 2 + 16;
        char* epi = smem + OFFA;
#pragma unroll
        for (int mt = 0; mt < 2; mt++) {
            const int r0 = mwarp * 32 + mt * 16 + (lane >> 2);
#pragma unroll
            for (int nt = 0; nt < NT; nt++) {
                const int c0 = nwarp * (NB / 2) + nt * 8 + (lane & 3) * 2;
                const float b0 = s_bias[c0], b1 = s_bias[c0 + 1];
                __half2 v0 = __floats2half2_rn(fmaxf(acc[mt][nt][0] + b0, 0.f),
                                               fmaxf(acc[mt][nt][1] + b1, 0.f));
                __half2 v1 = __floats2half2_rn(fmaxf(acc[mt][nt][2] + b0, 0.f),
                                               fmaxf(acc[mt][nt][3] + b1, 0.f));
                *(__half2*)(epi + r0 * ES + c0 * 2) = v0;
                *(__half2*)(epi + (r0 + 8) * ES + c0 * 2) = v1;
            }
        }
        __syncthreads();
        constexpr int ROWB = NB / 8;
        __half* outh = (__half*)outp;
#pragma unroll
        for (int i = 0; i < 8; i++) {
            int idx = tid + i * 256;
            int r2 = idx / ROWB;
            int j = idx & (ROWB - 1);
            uint4 v = *(const uint4*)(epi + r2 * ES + j * 16);
            int ohl = r2 >> LOG_OW, ow = r2 & (OW - 1);
            __half* dst = outh + (((size_t)n * OH + oh0 + ohl) * OW + ow) * OCTOT
                        + nblk * NB + j * 8;
            *(uint4*)dst = v;
        }
    } else {
        float* s_red = (float*)(smem + OFFA);
#pragma unroll
        for (int nt = 0; nt < NT; nt++) {
            const int c0 = nwarp * (NB / 2) + nt * 8 + (lane & 3) * 2;
            const float b0 = s_bias[c0], b1 = s_bias[c0 + 1];
            float s0 = 0.f, s1 = 0.f;
#pragma unroll
            for (int mt = 0; mt < 2; mt++) {
                s0 += fmaxf(acc[mt][nt][0] + b0, 0.f) + fmaxf(acc[mt][nt][2] + b0, 0.f);
                s1 += fmaxf(acc[mt][nt][1] + b1, 0.f) + fmaxf(acc[mt][nt][3] + b1, 0.f);
            }
#pragma unroll
            for (int off = 16; off >= 4; off >>= 1) {
                s0 += __shfl_xor_sync(0xffffffffu, s0, off);
                s1 += __shfl_xor_sync(0xffffffffu, s1, off);
            }
            if ((lane >> 2) == 0) {
                s_red[c0 * 4 + mwarp] = s0;
                s_red[(c0 + 1) * 4 + mwarp] = s1;
            }
        }
        __syncthreads();
        if (tid < NB) {
            float s = s_red[tid * 4] + s_red[tid * 4 + 1]
                    + s_red[tid * 4 + 2] + s_red[tid * 4 + 3];
            ((float*)outp)[((size_t)n * MBLK + mblk) * 256 + nblk * NB + tid] = s;
        }
    }
}

// ---------------------------------------------------------------------------
// Fused per-sample MLP chain — 512 threads, split-K on every layer.
// ---------------------------------------------------------------------------
__global__ void __launch_bounds__(512)
mlp_chain_kernel(const float* __restrict__ vpart, const float* __restrict__ prop,
                 const int* __restrict__ task_ids,
                 const float* __restrict__ p1_w, const float* __restrict__ p1_b,
                 const float* __restrict__ p2_w, const float* __restrict__ p2_b,
                 const float* __restrict__ f1_w, const float* __restrict__ f1_b,
                 const float* __restrict__ f2_w, const float* __restrict__ f2_b,
                 const float* __restrict__ task_emb,
                 const float* __restrict__ g_w, const float* __restrict__ g_b,
                 const float* __restrict__ h1_w, const float* __restrict__ h1_b,
                 const float* __restrict__ h2_w, const float* __restrict__ h2_b,
                 const float* __restrict__ h3_w, const float* __restrict__ h3_b,
                 float* __restrict__ out)
{
    const int n = blockIdx.x;
    const int tid = threadIdx.x;

    __shared__ float sA[320];
    __shared__ float sB[256];
    __shared__ float sP[512];
    __shared__ float sx[7];
    __shared__ float sh[64];

    if (tid < 256)
        sA[tid] = (vpart[((size_t)n * 2 + 0) * 256 + tid] +
                   vpart[((size_t)n * 2 + 1) * 256 + tid]) * (1.f / 256.f);
    if (tid < 7) sx[tid] = prop[n * 7 + tid];
    const int t = task_ids[n];
    __syncthreads();

    if (tid < 64) {
        float a = p1_b[tid];
#pragma unroll
        for (int i = 0; i < 7; i++) a += sx[i] * p1_w[i * 64 + tid];
        sh[tid] = fmaxf(a, 0.f);
    }
    __syncthreads();
    if (tid < 128) {
        const int o = tid & 63, kh = tid >> 6, k0 = kh * 32;
        float a0 = 0.f, a1 = 0.f, a2 = 0.f, a3 = 0.f;
#pragma unroll
        for (int i = 0; i < 32; i += 4) {
            int k = k0 + i;
            a0 += sh[k] * p2_w[k * 64 + o];
            a1 += sh[k + 1] * p2_w[(k + 1) * 64 + o];
            a2 += sh[k + 2] * p2_w[(k + 2) * 64 + o];
            a3 += sh[k + 3] * p2_w[(k + 3) * 64 + o];
        }
        sP[tid] = (a0 + a1) + (a2 + a3);
    }
    __syncthreads();
    if (tid < 64) sA[256 + tid] = sP[tid] + sP[tid + 64] + p2_b[tid];
    __syncthreads();

    {
        const int o = tid & 255, kh = tid >> 8, k0 = kh * 160;
        float a0 = 0.f, a1 = 0.f, a2 = 0.f, a3 = 0.f;
        for (int i = 0; i < 160; i += 4) {
            int k = k0 + i;
            a0 += sA[k] * f1_w[k * 256 + o];
            a1 += sA[k + 1] * f1_w[(k + 1) * 256 + o];
            a2 += sA[k + 2] * f1_w[(k + 2) * 256 + o];
            a3 += sA[k + 3] * f1_w[(k + 3) * 256 + o];
        }
        sP[tid] = (a0 + a1) + (a2 + a3);
    }
    __syncthreads();
    if (tid < 256) sB[tid] = fmaxf(sP[tid] + sP[tid + 256] + f1_b[tid], 0.f);
    __syncthreads();

    {
        const int o = tid & 255, kh = tid >> 8, k0 = kh * 128;
        float a0 = 0.f, a1 = 0.f, a2 = 0.f, a3 = 0.f;
        for (int i = 0; i < 128; i += 4) {
            int k = k0 + i;
            a0 += sB[k] * f2_w[k * 256 + o];
            a1 += sB[k + 1] * f2_w[(k + 1) * 256 + o];
            a2 += sB[k + 2] * f2_w[(k + 2) * 256 + o];
            a3 += sB[k + 3] * f2_w[(k + 3) * 256 + o];
        }
        sP[tid] = (a0 + a1) + (a2 + a3);
    }
    __syncthreads();
    if (tid < 256) sA[tid] = fmaxf(sP[tid] + sP[tid + 256] + f2_b[tid], 0.f);
    if (tid >= 256 && tid < 288) sA[tid] = task_emb[t * 32 + (tid - 256)];
    __syncthreads();

    {
        const int o = tid & 255, kh = tid >> 8, k0 = kh * 144;
        float a0 = 0.f, a1 = 0.f, a2 = 0.f, a3 = 0.f;
        for (int i = 0; i < 144; i += 4) {
            int k = k0 + i;
            a0 += sA[k] * g_w[k * 256 + o];
            a1 += sA[k + 1] * g_w[(k + 1) * 256 + o];
            a2 += sA[k + 2] * g_w[(k + 2) * 256 + o];
            a3 += sA[k + 3] * g_w[(k + 3) * 256 + o];
        }
        sP[tid] = (a0 + a1) + (a2 + a3);
    }
    __syncthreads();
    if (tid < 256) sB[tid] = fmaxf(sP[tid] + sP[tid + 256] + g_b[tid], 0.f);
    __syncthreads();

    {
        const float* w1 = h1_w + (size_t)t * ENC_DIM * HEAD_HID;
        const int o = tid & 127, kh = tid >> 7, k0 = kh * 64;
        float a0 = 0.f, a1 = 0.f, a2 = 0.f, a3 = 0.f;
        for (int i = 0; i < 64; i += 4) {
            int k = k0 + i;
            a0 += sB[k] * w1[k * 128 + o];
            a1 += sB[k + 1] * w1[(k + 1) * 128 + o];
            a2 += sB[k + 2] * w1[(k + 2) * 128 + o];
            a3 += sB[k + 3] * w1[(k + 3) * 128 + o];
        }
        sP[tid] = (a0 + a1) + (a2 + a3);
    }
    __syncthreads();
    if (tid < 128)
        sA[tid] = fmaxf(sP[tid] + sP[tid + 128] + sP[tid + 256] + sP[tid + 384]
                        + h1_b[t * 128 + tid], 0.f);
    __syncthreads();

    {
        const float* w2 = h2_w + (size_t)t * HEAD_HID * HEAD_HID;
        const int o = tid & 127, kh = tid >> 7, k0 = kh * 32;
        float a0 = 0.f, a1 = 0.f, a2 = 0.f, a3 = 0.f;
#pragma unroll
        for (int i = 0; i < 32; i += 4) {
            int k = k0 + i;
            a0 += sA[k] * w2[k * 128 + o];
            a1 += sA[k + 1] * w2[(k + 1) * 128 + o];
            a2 += sA[k + 2] * w2[(k + 2) * 128 + o];
            a3 += sA[k + 3] * w2[(k + 3) * 128 + o];
        }
        sP[tid] = (a0 + a1) + (a2 + a3);
    }
    __syncthreads();
    if (tid < 128)
        sB[tid] = fmaxf(sP[tid] + sP[tid + 128] + sP[tid + 256] + sP[tid + 384]
                        + h2_b[t * 128 + tid], 0.f);
    __syncthreads();

    if (tid < 128) {
        const float* w3 = h3_w + (size_t)t * HEAD_HID * 4;
        const int o = tid >> 5;
        const int l = tid & 31;
        float a = 0.f;
#pragma unroll
        for (int j = 0; j < 4; j++) a += sB[l + j * 32] * w3[(l + j * 32) * 4 + o];
#pragma unroll
        for (int d = 16; d > 0; d >>= 1) a += __shfl_xor_sync(0xffffffffu, a, d);
        if (l == 0) out[n * 4 + o] = a + h3_b[t * 4 + o];
    }
}

// ---------------------------------------------------------------------------
extern "C" void kernel_launch(void* const* d_in, const int* in_sizes, int n_in,
                              void* d_out, int out_size)
{
    const float* images = (const float*)d_in[0];
    const float* prop   = (const float*)d_in[1];
    const int*   tids   = (const int*)d_in[2];
    const float* c1_w = (const float*)d_in[3];
    const float* c1_b = (const float*)d_in[4];
    const float* c2_w = (const float*)d_in[5];
    const float* c2_b = (const float*)d_in[6];
    const float* c3_w = (const float*)d_in[7];
    const float* c3_b = (const float*)d_in[8];
    const float* p1_w = (const float*)d_in[9];
    const float* p1_b = (const float*)d_in[10];
    const float* p2_w = (const float*)d_in[11];
    const float* p2_b = (const float*)d_in[12];
    const float* f1_w = (const float*)d_in[13];
    const float* f1_b = (const float*)d_in[14];
    const float* f2_w = (const float*)d_in[15];
    const float* f2_b = (const float*)d_in[16];
    const float* temb = (const float*)d_in[17];
    const float* g_w  = (const float*)d_in[18];
    const float* g_b  = (const float*)d_in[19];
    const float* h1_w = (const float*)d_in[20];
    const float* h1_b = (const float*)d_in[21];
    const float* h2_w = (const float*)d_in[22];
    const float* h2_b = (const float*)d_in[23];
    const float* h3_w = (const float*)d_in[24];
    const float* h3_b = (const float*)d_in[25];
    float* out = (float*)d_out;

    __half *imgT, *act1, *act2, *w1r, *w2r, *w3r;
    float* vpart;
    cudaGetSymbolAddress((void**)&imgT, g_imgT);
    cudaGetSymbolAddress((void**)&act1, g_act1);
    cudaGetSymbolAddress((void**)&act2, g_act2);
    cudaGetSymbolAddress((void**)&w1r, g_w1rep);
    cudaGetSymbolAddress((void**)&w2r, g_w2rep);
    cudaGetSymbolAddress((void**)&w3r, g_w3rep);
    cudaGetSymbolAddress((void**)&vpart, g_vpart);

    // fused repack (img + all conv weights)
    repack_all<<<(IMG_ELEMS + W_ELEMS + 511) / 512, 512>>>(
        images, imgT, c1_w, c2_w, c3_w, w1r, w2r, w3r);

    // conv1: imgT -> act1 [256,64,64,64] NHWC half. 256 thr, NB=64, 3 CTA/SM
    {
        constexpr int SM = 1024 + 16384 + 8192;
        cudaFuncSetAttribute(conv1_kernel,
                             cudaFuncAttributeMaxDynamicSharedMemorySize, SM);
        conv1_kernel<<<BATCH * 32, 256, SM>>>(imgT, w1r, c1_b, act1);
    }
    // conv2: act1 -> act2 [256,32,32,128]. R7 config: NB=128, 2 CTA/SM
    {
        constexpr int SM = 50176 + 3 * (128 * 128);   // 99328
        auto k = conv_r7_kernel<64, 576, 128, 64, 64, 4, false>;
        cudaFuncSetAttribute(k, cudaFuncAttributeMaxDynamicSharedMemorySize, SM);
        k<<<BATCH * 8, 256, SM>>>(act1, w2r, c2_b, act2);
    }
    // conv3 + pool partials -> vpart. R7 config.
    {
        constexpr int SM = 50176 + 3 * (128 * 128);
        auto k = conv_r7_kernel<128, 1152, 256, 32, 32, 8, true>;
        cudaFuncSetAttribute(k, cudaFuncAttributeMaxDynamicSharedMemorySize, SM);
        k<<<BATCH * 2 * 2, 256, SM>>>(act2, w3r, c3_b, vpart);
    }

    mlp_chain_kernel<<<BATCH, 512>>>(
        vpart, prop, tids,
        p1_w, p1_b, p2_w, p2_b,
        f1_w, f1_b, f2_w, f2_b,
        temb, g_w, g_b,
        h1_w, h1_b, h2_w, h2_b, h3_w, h3_b,
        out);
}

// round 16
// speedup vs baseline: 1.0515x; 1.0515x over previous
#include <cuda_runtime.h>
#include <cuda_fp16.h>
#include <cstdint>

#define BATCH 256
#define ENC_DIM 256
#define HEAD_HID 128

// ---------------------------------------------------------------------------
// Scratch (static __device__ — no allocations allowed)
// ---------------------------------------------------------------------------
__device__ __half g_imgT[(size_t)BATCH * 130 * 130 * 4];        // padded NHWC4
__device__ __half g_act1[(size_t)BATCH * 64 * 64 * 64];         // conv1 out NHWC
__device__ __half g_act2[(size_t)BATCH * 32 * 32 * 128];        // conv2 out NHWC
__device__ __half g_w1rep[64 * 64];
__device__ __half g_w2rep[128 * 576];
__device__ __half g_w3rep[256 * 1152];
__device__ float  g_vpart[(size_t)BATCH * 2 * 256];

// ---------------------------------------------------------------------------
// helpers
// ---------------------------------------------------------------------------
__device__ __forceinline__ uint32_t smem_u32(const void* p) {
    uint32_t a;
    asm("{ .reg .u64 t; cvta.to.shared.u64 t, %1; cvt.u32.u64 %0, t; }"
        : "=r"(a) : "l"(p));
    return a;
}
__device__ __forceinline__ uint32_t swz(uint32_t off) {
    return off ^ ((off >> 3) & 0x70);
}
__device__ __forceinline__ void ldm_x4(uint32_t r[4], uint32_t addr) {
    asm volatile("ldmatrix.sync.aligned.m8n8.x4.shared.b16 {%0,%1,%2,%3}, [%4];"
                 : "=r"(r[0]), "=r"(r[1]), "=r"(r[2]), "=r"(r[3]) : "r"(addr));
}
__device__ __forceinline__ void mma_f16(float c[4], const uint32_t a[4],
                                        uint32_t b0, uint32_t b1) {
    asm volatile(
        "mma.sync.aligned.m16n8k16.row.col.f32.f16.f16.f32 "
        "{%0,%1,%2,%3},{%4,%5,%6,%7},{%8,%9},{%0,%1,%2,%3};"
        : "+f"(c[0]), "+f"(c[1]), "+f"(c[2]), "+f"(c[3])
        : "r"(a[0]), "r"(a[1]), "r"(a[2]), "r"(a[3]), "r"(b0), "r"(b1));
}
#define CP_COMMIT() asm volatile("cp.async.commit_group;" ::: "memory")
#define CP_WAIT0()  asm volatile("cp.async.wait_group 0;" ::: "memory")
#define CP_WAIT1()  asm volatile("cp.async.wait_group 1;" ::: "memory")

// ---------------------------------------------------------------------------
// Fused repack kernel (one launch): img -> padded NHWC4 half, weights -> K-major
// ---------------------------------------------------------------------------
#define IMG_ELEMS (BATCH * 130 * 130)        // 4326400
#define W_ELEMS   (4096 + 73728 + 294912)    // 372736

__device__ __forceinline__ void repack_one(const float* __restrict__ src,
                                           __half* __restrict__ dst,
                                           int idx, int IC, int ICP, int K)
{
    int oc = idx / K;
    int k = idx - oc * K;
    int tap = k / ICP;
    int ic = k - tap * ICP;
    float v = (tap < 9 && ic < IC) ? src[(oc * IC + ic) * 9 + tap] : 0.f;
    dst[idx] = __float2half_rn(v);
}

__global__ void repack_all(const float* __restrict__ img, __half* __restrict__ dimg,
                           const float* __restrict__ c1w, const float* __restrict__ c2w,
                           const float* __restrict__ c3w,
                           __half* __restrict__ w1, __half* __restrict__ w2,
                           __half* __restrict__ w3)
{
    int idx = blockIdx.x * 512 + threadIdx.x;
    if (idx < IMG_ELEMS) {
        int n = idx / 16900;
        int r = idx - n * 16900;
        int ihp = r / 130;
        int iwp = r - ihp * 130;
        int ih = ihp - 1, iw = iwp - 1;
        float c0 = 0.f, c1 = 0.f, c2 = 0.f;
        if ((unsigned)ih < 128u && (unsigned)iw < 128u) {
            size_t b = (size_t)n * 3 * 16384 + ih * 128 + iw;
            c0 = img[b]; c1 = img[b + 16384]; c2 = img[b + 32768];
        }
        __half2 lo = __floats2half2_rn(c0, c1);
        __half2 hi = __floats2half2_rn(c2, 0.f);
        uint2 v;
        v.x = *(uint32_t*)&lo;
        v.y = *(uint32_t*)&hi;
        *(uint2*)(dimg + (size_t)idx * 4) = v;
    } else {
        int w = idx - IMG_ELEMS;
        if (w < 4096) repack_one(c1w, w1, w, 3, 4, 64);
        else if (w < 4096 + 73728) repack_one(c2w, w2, w - 4096, 64, 64, 576);
        else if (w < W_ELEMS) repack_one(c3w, w3, w - 4096 - 73728, 128, 128, 1152);
    }
}

// ---------------------------------------------------------------------------
// conv1 kernel: 256 threads, NB=64, NCH=1, 3 CTA/SM, KSTEPS=3 (K 36->48).
// Padding bytes 72..95 of each A row zeroed precisely (taps write 0..71).
// ---------------------------------------------------------------------------
__global__ void __launch_bounds__(256, 3)
conv1_kernel(const __half* __restrict__ in, const __half* __restrict__ wrep,
             const float* __restrict__ bias, __half* __restrict__ outp)
{
    constexpr int OW = 64, OH = 64;
    constexpr int NB = 64;
    constexpr uint32_t OFFA = 1024;
    constexpr uint32_t OFFB = OFFA + 16384;

    extern __shared__ char smem[];
    const uint32_t sb = smem_u32(smem);
    float* s_bias = (float*)smem;

    const int bid = blockIdx.x;
    const int n = bid >> 5;
    const int mblk = bid & 31;
    const int oh0 = mblk * 2;

    const int tid = threadIdx.x;
    const int warp = tid >> 5;
    const int lane = tid & 31;
    const int mwarp = warp >> 1;
    const int nwarp = warp & 1;

    if (tid < NB) s_bias[tid] = bias[tid];

    if (tid < 128) {
        const uint32_t rb = OFFA + (uint32_t)tid * 128;
        *(uint64_t*)(smem + swz(rb + 72)) = 0ull;
        *(uint64_t*)(smem + swz(rb + 80)) = 0ull;
        *(uint64_t*)(smem + swz(rb + 88)) = 0ull;
    }

    {
        const int am = tid >> 1;
        const int a_ohl = am >> 6;
        const int a_ow = am & 63;
        const int ihb = (oh0 + a_ohl) * 2;
        const int iwb = a_ow * 2;
#pragma unroll
        for (int i = 0; i < 5; i++) {
            int j = (tid & 1) + 2 * i;
            if (j <= 8) {
                int kh = j / 3, kw = j - kh * 3;
                const __half* src = in + (((size_t)n * 130 + ihb + kh) * 130 + iwb + kw) * 4;
                uint32_t dst = sb + OFFA + swz((uint32_t)(am * 128 + j * 8));
                asm volatile("cp.async.ca.shared.global [%0], [%1], 8;"
                             :: "r"(dst), "l"(src));
            }
        }
        const int bn = tid >> 2;
        const int bseg = (tid & 3) * 2;
#pragma unroll
        for (int i = 0; i < 2; i++) {
            const __half* src = wrep + (size_t)bn * 64 + (bseg + i) * 8;
            uint32_t dst = sb + OFFB + swz((uint32_t)(bn * 128 + (bseg + i) * 16));
            asm volatile("cp.async.cg.shared.global [%0], [%1], 16;"
                         :: "r"(dst), "l"(src));
        }
    }
    CP_COMMIT();
    CP_WAIT0();
    __syncthreads();

    float acc[2][4][4];
#pragma unroll
    for (int mt = 0; mt < 2; mt++)
#pragma unroll
        for (int nt = 0; nt < 4; nt++)
#pragma unroll
            for (int i = 0; i < 4; i++) acc[mt][nt][i] = 0.f;

#pragma unroll
    for (int ks = 0; ks < 3; ks++) {
        const uint32_t colb = ks * 32 + ((lane >> 4) << 4);
        uint32_t a[2][4], bf[2][4];
#pragma unroll
        for (int mt = 0; mt < 2; mt++) {
            const uint32_t row = mwarp * 32 + mt * 16 + (lane & 15);
            ldm_x4(a[mt], sb + OFFA + swz(row * 128 + colb));
        }
#pragma unroll
        for (int np = 0; np < 2; np++) {
            const uint32_t row = nwarp * 32 + np * 16 + (lane & 15);
            ldm_x4(bf[np], sb + OFFB + swz(row * 128 + colb));
        }
#pragma unroll
        for (int mt = 0; mt < 2; mt++)
#pragma unroll
            for (int nt = 0; nt < 4; nt++)
                mma_f16(acc[mt][nt], a[mt], bf[nt >> 1][nt & 1],
                        bf[nt >> 1][2 + (nt & 1)]);
    }
    __syncthreads();

    constexpr uint32_t ES = NB * 2 + 16;
    char* epi = smem + OFFA;
#pragma unroll
    for (int mt = 0; mt < 2; mt++) {
        const int r0 = mwarp * 32 + mt * 16 + (lane >> 2);
#pragma unroll
        for (int nt = 0; nt < 4; nt++) {
            const int c0 = nwarp * 32 + nt * 8 + (lane & 3) * 2;
            const float b0 = s_bias[c0], b1 = s_bias[c0 + 1];
            __half2 v0 = __floats2half2_rn(fmaxf(acc[mt][nt][0] + b0, 0.f),
                                           fmaxf(acc[mt][nt][1] + b1, 0.f));
            __half2 v1 = __floats2half2_rn(fmaxf(acc[mt][nt][2] + b0, 0.f),
                                           fmaxf(acc[mt][nt][3] + b1, 0.f));
            *(__half2*)(epi + r0 * ES + c0 * 2) = v0;
            *(__half2*)(epi + (r0 + 8) * ES + c0 * 2) = v1;
        }
    }
    __syncthreads();
#pragma unroll
    for (int i = 0; i < 4; i++) {
        int idx = tid + i * 256;
        int r2 = idx >> 3;
        int j = idx & 7;
        uint4 v = *(const uint4*)(epi + r2 * ES + j * 16);
        int ohl = r2 >> 6, ow = r2 & 63;
        __half* dst = outp + (((size_t)n * OH + oh0 + ohl) * OW + ow) * 64 + j * 8;
        *(uint4*)dst = v;
    }
}

// ---------------------------------------------------------------------------
// R7-proven conv (conv2/conv3): 256 thr, 8 warps 4Mx2N, NB=128, 2 CTA/SM.
// 3-buffer cp.async pipeline, one sync per chunk, wait->sync->mma->issue.
// do_mma is the R7-exact form (all tweaks since were neutral or worse).
// ---------------------------------------------------------------------------
template <int ICP, int KTOT, int OCTOT, int IH, int IW, int OH_TILE, bool FUSE_POOL>
__global__ void __launch_bounds__(256, 2)
conv_r7_kernel(const __half* __restrict__ in, const __half* __restrict__ wrep,
               const float* __restrict__ bias, void* __restrict__ outp)
{
    constexpr int OH = IH / 2, OW = IW / 2;
    constexpr int LOG_OW = (OW == 64) ? 6 : (OW == 32) ? 5 : 4;
    constexpr int NB = 128;
    constexpr int NCH = KTOT / 64;
    constexpr int CPT = ICP / 64;
    constexpr int MBLK = OH / OH_TILE;
    constexpr int NBLK = OCTOT / NB;
    constexpr int NT = 8;
    constexpr int NP = 4;
    constexpr uint32_t OFFA = 1024;
    constexpr uint32_t ABUF = 16384;
    constexpr uint32_t OFFB = OFFA + 3 * ABUF;
    constexpr uint32_t BBUF = NB * 128;

    extern __shared__ char smem[];
    const uint32_t sb = smem_u32(smem);
    float* s_bias = (float*)smem;

    const int bid = blockIdx.x;
    const int n = bid / (MBLK * NBLK);
    const int r = bid - n * (MBLK * NBLK);
    const int mblk = r / NBLK;
    const int nblk = r - mblk * NBLK;
    const int oh0 = mblk * OH_TILE;

    const int tid = threadIdx.x;
    const int warp = tid >> 5;
    const int lane = tid & 31;
    const int mwarp = warp >> 1;
    const int nwarp = warp & 1;

    if (tid < NB) s_bias[tid] = bias[nblk * NB + tid];

    const int am = tid >> 1;
    const int a_ohl = am >> LOG_OW;
    const int a_ow = am & (OW - 1);

    auto issueA = [&](int c, uint32_t abase) {
        const int tap = c / CPT;
        const int ic0 = (c & (CPT - 1)) * 64;
        const int kh = tap / 3, kw = tap - kh * 3;
        const int ih = (oh0 + a_ohl) * 2 - 1 + kh;
        const int iw = a_ow * 2 - 1 + kw;
        const bool valid = ((unsigned)ih < (unsigned)IH) &&
                           ((unsigned)iw < (unsigned)IW);
        const __half* src = valid
            ? in + (((size_t)n * IH + ih) * IW + iw) * ICP + ic0 : in;
        const int sz = valid ? 16 : 0;
#pragma unroll
        for (int i = 0; i < 4; i++) {
            int u = (tid & 1) * 4 + i;
            uint32_t dst = sb + abase + swz((uint32_t)(am * 128 + u * 16));
            asm volatile("cp.async.cg.shared.global [%0], [%1], 16, %2;"
                         :: "r"(dst), "l"(src + u * 8), "r"(sz));
        }
    };
    auto issueB = [&](int c, uint32_t bbase) {
#pragma unroll
        for (int i = 0; i < 4; i++) {
            int u = tid * 4 + i;
            int row = u >> 3, j = u & 7;
            const __half* src = wrep + (size_t)(nblk * NB + row) * KTOT + c * 64 + j * 8;
            uint32_t dst = sb + bbase + swz((uint32_t)(row * 128 + j * 16));
            asm volatile("cp.async.cg.shared.global [%0], [%1], 16;"
                         :: "r"(dst), "l"(src));
        }
    };

    float acc[2][NT][4];
#pragma unroll
    for (int mt = 0; mt < 2; mt++)
#pragma unroll
        for (int nt = 0; nt < NT; nt++)
#pragma unroll
            for (int i = 0; i < 4; i++) acc[mt][nt][i] = 0.f;

    auto do_mma = [&](uint32_t abase, uint32_t bbase) {
#pragma unroll
        for (int ks = 0; ks < 4; ks++) {
            const uint32_t colb = ks * 32 + ((lane >> 4) << 4);
            uint32_t a[2][4], bf[NP][4];
#pragma unroll
            for (int mt = 0; mt < 2; mt++) {
                const uint32_t row = mwarp * 32 + mt * 16 + (lane & 15);
                ldm_x4(a[mt], sb + abase + swz(row * 128 + colb));
            }
#pragma unroll
            for (int np = 0; np < NP; np++) {
                const uint32_t row = nwarp * (NB / 2) + np * 16 + (lane & 15);
                ldm_x4(bf[np], sb + bbase + swz(row * 128 + colb));
            }
#pragma unroll
            for (int mt = 0; mt < 2; mt++)
#pragma unroll
                for (int nt = 0; nt < NT; nt++)
                    mma_f16(acc[mt][nt], a[mt], bf[nt >> 1][nt & 1],
                            bf[nt >> 1][2 + (nt & 1)]);
        }
    };

    issueB(0, OFFB);
    issueA(0, OFFA);
    CP_COMMIT();
    issueB(1, OFFB + BBUF);
    issueA(1, OFFA + ABUF);
    CP_COMMIT();

    int bi = 0;
#pragma unroll 1
    for (int c = 0; c < NCH; c++) {
        if (c + 1 < NCH) { CP_WAIT1(); } else { CP_WAIT0(); }
        __syncthreads();
        do_mma(OFFA + (uint32_t)bi * ABUF, OFFB + (uint32_t)bi * BBUF);
        if (c + 2 < NCH) {
            int b2 = bi + 2; if (b2 >= 3) b2 -= 3;
            issueB(c + 2, OFFB + (uint32_t)b2 * BBUF);
            issueA(c + 2, OFFA + (uint32_t)b2 * ABUF);
            CP_COMMIT();
        }
        if (++bi == 3) bi = 0;
    }
    __syncthreads();

    if (!FUSE_POOL) {
        constexpr uint32_t ES = NB * 2 + 16;
        char* epi = smem + OFFA;
#pragma unroll
        for (int mt = 0; mt < 2; mt++) {
            const int r0 = mwarp * 32 + mt * 16 + (lane >> 2);
#pragma unroll
            for (int nt = 0; nt < NT; nt++) {
                const int c0 = nwarp * (NB / 2) + nt * 8 + (lane & 3) * 2;
                const float b0 = s_bias[c0], b1 = s_bias[c0 + 1];
                __half2 v0 = __floats2half2_rn(fmaxf(acc[mt][nt][0] + b0, 0.f),
                                               fmaxf(acc[mt][nt][1] + b1, 0.f));
                __half2 v1 = __floats2half2_rn(fmaxf(acc[mt][nt][2] + b0, 0.f),
                                               fmaxf(acc[mt][nt][3] + b1, 0.f));
                *(__half2*)(epi + r0 * ES + c0 * 2) = v0;
                *(__half2*)(epi + (r0 + 8) * ES + c0 * 2) = v1;
            }
        }
        __syncthreads();
        constexpr int ROWB = NB / 8;
        __half* outh = (__half*)outp;
#pragma unroll
        for (int i = 0; i < 8; i++) {
            int idx = tid + i * 256;
            int r2 = idx / ROWB;
            int j = idx & (ROWB - 1);
            uint4 v = *(const uint4*)(epi + r2 * ES + j * 16);
            int ohl = r2 >> LOG_OW, ow = r2 & (OW - 1);
            __half* dst = outh + (((size_t)n * OH + oh0 + ohl) * OW + ow) * OCTOT
                        + nblk * NB + j * 8;
            *(uint4*)dst = v;
        }
    } else {
        float* s_red = (float*)(smem + OFFA);
#pragma unroll
        for (int nt = 0; nt < NT; nt++) {
            const int c0 = nwarp * (NB / 2) + nt * 8 + (lane & 3) * 2;
            const float b0 = s_bias[c0], b1 = s_bias[c0 + 1];
            float s0 = 0.f, s1 = 0.f;
#pragma unroll
            for (int mt = 0; mt < 2; mt++) {
                s0 += fmaxf(acc[mt][nt][0] + b0, 0.f) + fmaxf(acc[mt][nt][2] + b0, 0.f);
                s1 += fmaxf(acc[mt][nt][1] + b1, 0.f) + fmaxf(acc[mt][nt][3] + b1, 0.f);
            }
#pragma unroll
            for (int off = 16; off >= 4; off >>= 1) {
                s0 += __shfl_xor_sync(0xffffffffu, s0, off);
                s1 += __shfl_xor_sync(0xffffffffu, s1, off);
            }
            if ((lane >> 2) == 0) {
                s_red[c0 * 4 + mwarp] = s0;
                s_red[(c0 + 1) * 4 + mwarp] = s1;
            }
        }
        __syncthreads();
        if (tid < NB) {
            float s = s_red[tid * 4] + s_red[tid * 4 + 1]
                    + s_red[tid * 4 + 2] + s_red[tid * 4 + 3];
            ((float*)outp)[((size_t)n * MBLK + mblk) * 256 + nblk * NB + tid] = s;
        }
    }
}

// ---------------------------------------------------------------------------
// Fused per-sample MLP chain — 512 threads.
// Trunk layers: 4 outputs/thread via float4 weight loads (w[k*OUT+o] is
// contiguous over o), split-K across thread groups, smem partial reduction.
// LSU instr per layer drops ~4x vs scalar split-K.
// ---------------------------------------------------------------------------
__global__ void __launch_bounds__(512)
mlp_chain_kernel(const float* __restrict__ vpart, const float* __restrict__ prop,
                 const int* __restrict__ task_ids,
                 const float* __restrict__ p1_w, const float* __restrict__ p1_b,
                 const float* __restrict__ p2_w, const float* __restrict__ p2_b,
                 const float* __restrict__ f1_w, const float* __restrict__ f1_b,
                 const float* __restrict__ f2_w, const float* __restrict__ f2_b,
                 const float* __restrict__ task_emb,
                 const float* __restrict__ g_w, const float* __restrict__ g_b,
                 const float* __restrict__ h1_w, const float* __restrict__ h1_b,
                 const float* __restrict__ h2_w, const float* __restrict__ h2_b,
                 const float* __restrict__ h3_w, const float* __restrict__ h3_b,
                 float* __restrict__ out)
{
    const int n = blockIdx.x;
    const int tid = threadIdx.x;

    __shared__ float sA[320];
    __shared__ float sB[256];
    __shared__ float sP[2048];    // 512 threads x float4 partials
    __shared__ float sx[7];
    __shared__ float sh[64];

    if (tid < 256)
        sA[tid] = (vpart[((size_t)n * 2 + 0) * 256 + tid] +
                   vpart[((size_t)n * 2 + 1) * 256 + tid]) * (1.f / 256.f);
    if (tid < 7) sx[tid] = prop[n * 7 + tid];
    const int t = task_ids[n];
    __syncthreads();

    // p1: 7 -> 64, relu (direct)
    if (tid < 64) {
        float a = p1_b[tid];
#pragma unroll
        for (int i = 0; i < 7; i++) a += sx[i] * p1_w[i * 64 + tid];
        sh[tid] = fmaxf(a, 0.f);
    }
    __syncthreads();

    // generic split-K float4 layer step (compute phase)
    // OG output-groups of 4, GK = 512/OG k-groups, KPG k per group
#define LAYER_COMPUTE(W, SIN, OUT, OG, KPG)                                    \
    {                                                                          \
        const int og = tid & (OG - 1);                                         \
        const int kg = tid / OG;                                               \
        const int k0 = kg * KPG;                                               \
        float4 acc = make_float4(0.f, 0.f, 0.f, 0.f);                          \
        _Pragma("unroll 4")                                                    \
        for (int i = 0; i < KPG; i++) {                                        \
            const float a = SIN[k0 + i];                                       \
            const float4 w4 = *(const float4*)&W[(size_t)(k0 + i) * OUT + og * 4]; \
            acc.x += a * w4.x; acc.y += a * w4.y;                              \
            acc.z += a * w4.z; acc.w += a * w4.w;                              \
        }                                                                      \
        *(float4*)&sP[tid * 4] = acc;                                          \
    }
#define LAYER_REDUCE(BIASEXPR, SOUT, OUT, OG, GK, RELU)                        \
    if (tid < OUT) {                                                           \
        float s = (BIASEXPR);                                                  \
        const int base = ((tid >> 2) << 2) + (tid & 3);                        \
        _Pragma("unroll")                                                      \
        for (int kg = 0; kg < GK; kg++) s += sP[kg * (OG * 4) + base];         \
        SOUT[tid] = RELU ? fmaxf(s, 0.f) : s;                                  \
    }

    // p2: 64 -> 64 (no relu). OG=16, GK=32, KPG=2. out -> sA[256..319]
    LAYER_COMPUTE(p2_w, sh, 64, 16, 2);
    __syncthreads();
    if (tid < 64) {
        float s = p2_b[tid];
        const int base = ((tid >> 2) << 2) + (tid & 3);
#pragma unroll
        for (int kg = 0; kg < 32; kg++) s += sP[kg * 64 + base];
        sA[256 + tid] = s;
    }
    __syncthreads();

    // f1: 320 -> 256, relu. OG=64, GK=8, KPG=40. sA -> sB
    LAYER_COMPUTE(f1_w, sA, 256, 64, 40);
    __syncthreads();
    LAYER_REDUCE(f1_b[tid], sB, 256, 64, 8, true);
    __syncthreads();

    // f2: 256 -> 256, relu. KPG=32. sB -> sA; emb into sA[256..287]
    LAYER_COMPUTE(f2_w, sB, 256, 64, 32);
    __syncthreads();
    LAYER_REDUCE(f2_b[tid], sA, 256, 64, 8, true);
    if (tid >= 256 && tid < 288) sA[tid] = task_emb[t * 32 + (tid - 256)];
    __syncthreads();

    // g: 288 -> 256, relu. KPG=36. sA -> sB
    LAYER_COMPUTE(g_w, sA, 256, 64, 36);
    __syncthreads();
    LAYER_REDUCE(g_b[tid], sB, 256, 64, 8, true);
    __syncthreads();

    // h1: 256 -> 128, relu. OG=32, GK=16, KPG=16. sB -> sA
    {
        const float* w1 = h1_w + (size_t)t * ENC_DIM * HEAD_HID;
        LAYER_COMPUTE(w1, sB, 128, 32, 16);
    }
    __syncthreads();
    LAYER_REDUCE(h1_b[t * 128 + tid], sA, 128, 32, 16, true);
    __syncthreads();

    // h2: 128 -> 128, relu. KPG=8. sA -> sB
    {
        const float* w2 = h2_w + (size_t)t * HEAD_HID * HEAD_HID;
        LAYER_COMPUTE(w2, sA, 128, 32, 8);
    }
    __syncthreads();
    LAYER_REDUCE(h2_b[t * 128 + tid], sB, 128, 32, 16, true);
    __syncthreads();

    // h3: 128 -> 4, one warp per output
    if (tid < 128) {
        const float* w3 = h3_w + (size_t)t * HEAD_HID * 4;
        const int o = tid >> 5;
        const int l = tid & 31;
        float a = 0.f;
#pragma unroll
        for (int j = 0; j < 4; j++) a += sB[l + j * 32] * w3[(l + j * 32) * 4 + o];
#pragma unroll
        for (int d = 16; d > 0; d >>= 1) a += __shfl_xor_sync(0xffffffffu, a, d);
        if (l == 0) out[n * 4 + o] = a + h3_b[t * 4 + o];
    }
#undef LAYER_COMPUTE
#undef LAYER_REDUCE
}

// ---------------------------------------------------------------------------
extern "C" void kernel_launch(void* const* d_in, const int* in_sizes, int n_in,
                              void* d_out, int out_size)
{
    const float* images = (const float*)d_in[0];
    const float* prop   = (const float*)d_in[1];
    const int*   tids   = (const int*)d_in[2];
    const float* c1_w = (const float*)d_in[3];
    const float* c1_b = (const float*)d_in[4];
    const float* c2_w = (const float*)d_in[5];
    const float* c2_b = (const float*)d_in[6];
    const float* c3_w = (const float*)d_in[7];
    const float* c3_b = (const float*)d_in[8];
    const float* p1_w = (const float*)d_in[9];
    const float* p1_b = (const float*)d_in[10];
    const float* p2_w = (const float*)d_in[11];
    const float* p2_b = (const float*)d_in[12];
    const float* f1_w = (const float*)d_in[13];
    const float* f1_b = (const float*)d_in[14];
    const float* f2_w = (const float*)d_in[15];
    const float* f2_b = (const float*)d_in[16];
    const float* temb = (const float*)d_in[17];
    const float* g_w  = (const float*)d_in[18];
    const float* g_b  = (const float*)d_in[19];
    const float* h1_w = (const float*)d_in[20];
    const float* h1_b = (const float*)d_in[21];
    const float* h2_w = (const float*)d_in[22];
    const float* h2_b = (const float*)d_in[23];
    const float* h3_w = (const float*)d_in[24];
    const float* h3_b = (const float*)d_in[25];
    float* out = (float*)d_out;

    __half *imgT, *act1, *act2, *w1r, *w2r, *w3r;
    float* vpart;
    cudaGetSymbolAddress((void**)&imgT, g_imgT);
    cudaGetSymbolAddress((void**)&act1, g_act1);
    cudaGetSymbolAddress((void**)&act2, g_act2);
    cudaGetSymbolAddress((void**)&w1r, g_w1rep);
    cudaGetSymbolAddress((void**)&w2r, g_w2rep);
    cudaGetSymbolAddress((void**)&w3r, g_w3rep);
    cudaGetSymbolAddress((void**)&vpart, g_vpart);

    // fused repack (img + all conv weights)
    repack_all<<<(IMG_ELEMS + W_ELEMS + 511) / 512, 512>>>(
        images, imgT, c1_w, c2_w, c3_w, w1r, w2r, w3r);

    // conv1: imgT -> act1 [256,64,64,64] NHWC half. 256 thr, NB=64, 3 CTA/SM
    {
        constexpr int SM = 1024 + 16384 + 8192;
        cudaFuncSetAttribute(conv1_kernel,
                             cudaFuncAttributeMaxDynamicSharedMemorySize, SM);
        conv1_kernel<<<BATCH * 32, 256, SM>>>(imgT, w1r, c1_b, act1);
    }
    // conv2: act1 -> act2 [256,32,32,128]. R7 config: NB=128, 2 CTA/SM
    {
        constexpr int SM = 50176 + 3 * (128 * 128);   // 99328
        auto k = conv_r7_kernel<64, 576, 128, 64, 64, 4, false>;
        cudaFuncSetAttribute(k, cudaFuncAttributeMaxDynamicSharedMemorySize, SM);
        k<<<BATCH * 8, 256, SM>>>(act1, w2r, c2_b, act2);
    }
    // conv3 + pool partials -> vpart. R7 config.
    {
        constexpr int SM = 50176 + 3 * (128 * 128);
        auto k = conv_r7_kernel<128, 1152, 256, 32, 32, 8, true>;
        cudaFuncSetAttribute(k, cudaFuncAttributeMaxDynamicSharedMemorySize, SM);
        k<<<BATCH * 2 * 2, 256, SM>>>(act2, w3r, c3_b, vpart);
    }

    mlp_chain_kernel<<<BATCH, 512>>>(
        vpart, prop, tids,
        p1_w, p1_b, p2_w, p2_b,
        f1_w, f1_b, f2_w, f2_b,
        temb, g_w, g_b,
        h1_w, h1_b, h2_w, h2_b, h3_w, h3_b,
        out);
}

// round 17
// speedup vs baseline: 1.1148x; 1.0602x over previous
#include <cuda_runtime.h>
#include <cuda_fp16.h>
#include <cstdint>

#define BATCH 256
#define ENC_DIM 256
#define HEAD_HID 128

// ---------------------------------------------------------------------------
// Scratch (static __device__ — no allocations allowed)
// ---------------------------------------------------------------------------
__device__ __half g_imgT[(size_t)BATCH * 130 * 130 * 4];        // padded NHWC4
__device__ __half g_act1[(size_t)BATCH * 64 * 64 * 64];         // conv1 out NHWC
__device__ __half g_act2[(size_t)BATCH * 32 * 32 * 128];        // conv2 out NHWC
__device__ __half g_w1rep[64 * 64];                             // K-major (conv1)
__device__ __half g_w2rep[128 * 576];                           // swizzled blocks
__device__ __half g_w3rep[256 * 1152];                          // swizzled blocks
__device__ float  g_vpart[(size_t)BATCH * 2 * 256];

// ---------------------------------------------------------------------------
// helpers
// ---------------------------------------------------------------------------
__device__ __forceinline__ uint32_t smem_u32(const void* p) {
    uint32_t a;
    asm("{ .reg .u64 t; cvta.to.shared.u64 t, %1; cvt.u32.u64 %0, t; }"
        : "=r"(a) : "l"(p));
    return a;
}
__device__ __forceinline__ uint32_t swz(uint32_t off) {
    return off ^ ((off >> 3) & 0x70);
}
__device__ __forceinline__ void ldm_x4(uint32_t r[4], uint32_t addr) {
    asm volatile("ldmatrix.sync.aligned.m8n8.x4.shared.b16 {%0,%1,%2,%3}, [%4];"
                 : "=r"(r[0]), "=r"(r[1]), "=r"(r[2]), "=r"(r[3]) : "r"(addr));
}
__device__ __forceinline__ void mma_f16(float c[4], const uint32_t a[4],
                                        uint32_t b0, uint32_t b1) {
    asm volatile(
        "mma.sync.aligned.m16n8k16.row.col.f32.f16.f16.f32 "
        "{%0,%1,%2,%3},{%4,%5,%6,%7},{%8,%9},{%0,%1,%2,%3};"
        : "+f"(c[0]), "+f"(c[1]), "+f"(c[2]), "+f"(c[3])
        : "r"(a[0]), "r"(a[1]), "r"(a[2]), "r"(a[3]), "r"(b0), "r"(b1));
}
#define CP_COMMIT() asm volatile("cp.async.commit_group;" ::: "memory")
#define CP_WAIT0()  asm volatile("cp.async.wait_group 0;" ::: "memory")
#define CP_WAIT1()  asm volatile("cp.async.wait_group 1;" ::: "memory")

#define MBARRIER_INIT(mb, cnt) \
    asm volatile("mbarrier.init.shared.b64 [%0], %1;" \
                 :: "r"((uint32_t)(mb)), "r"((uint32_t)(cnt)) : "memory")
#define MBARRIER_EXPECT_TX(mb, bytes) \
    asm volatile("mbarrier.arrive.expect_tx.shared.b64 _, [%0], %1;" \
                 :: "r"((uint32_t)(mb)), "r"((uint32_t)(bytes)) : "memory")
#define CP_ASYNC_BULK(dst, src, bytes, mb) \
    asm volatile("cp.async.bulk.shared::cta.global.mbarrier::complete_tx::bytes " \
                 "[%0], [%1], %2, [%3];" \
                 :: "r"((uint32_t)(dst)), "l"(src), "r"((uint32_t)(bytes)), \
                    "r"((uint32_t)(mb)) : "memory")
#define MBARRIER_WAIT_PARITY(mb, ph) do { \
    uint32_t _m = (uint32_t)(mb), _p = (uint32_t)(ph), _d; \
    asm volatile("{\n\t.reg .pred p;\n\t" \
        "mbarrier.try_wait.parity.acquire.cta.shared::cta.b64 p, [%1], %2;\n\t" \
        "selp.b32 %0, 1, 0, p;\n\t}" : "=r"(_d) : "r"(_m), "r"(_p) : "memory"); \
    if (!_d) { \
        asm volatile("{\n\t.reg .pred P1;\n\tWL_%=:\n\t" \
            "mbarrier.try_wait.parity.acquire.cta.shared::cta.b64 P1, [%0], %1, 0x989680;\n\t" \
            "@P1 bra.uni WD_%=;\n\tbra.uni WL_%=;\n\tWD_%=:\n\t}" \
            :: "r"(_m), "r"(_p) : "memory"); \
    } \
} while (0)

// ---------------------------------------------------------------------------
// Fused repack (one launch):
//   img -> padded NHWC4 half
//   w1  -> K-major rows (conv1 path, unchanged)
//   w2/w3 -> PRE-SWIZZLED 16KB blocks [(nblk*NCH + c)][8192 halves], laid out
//            exactly as the smem B tile (dst[b] = weights[swz(b)] via
//            involution), so conv2/3 can cp.async.bulk them verbatim.
// ---------------------------------------------------------------------------
#define IMG_ELEMS (BATCH * 130 * 130)        // 4326400
#define W1_ELEMS  4096
#define W2_ELEMS  73728
#define W3_ELEMS  294912

__device__ __forceinline__ void repack_w1(const float* __restrict__ src,
                                          __half* __restrict__ dst, int idx)
{
    int oc = idx >> 6;
    int k = idx & 63;
    int tap = k >> 2;
    int ic = k & 3;
    float v = (tap < 9 && ic < 3) ? src[(oc * 3 + ic) * 9 + tap] : 0.f;
    dst[idx] = __float2half_rn(v);
}

// swizzled-block repack for conv2/conv3 weights
__device__ __forceinline__ void repack_wswz(const float* __restrict__ src,
                                            __half* __restrict__ dst,
                                            int h, int IC, int ICP, int NCH)
{
    int blk = h >> 13;                 // 8192 halves per 16KB block
    int pos = h & 8191;
    int nblk = blk / NCH;
    int c = blk - nblk * NCH;
    uint32_t lb = swz((uint32_t)(pos * 2));   // involution: source linear byte
    int row = lb >> 7;                 // 0..127
    int kj = (lb & 127) >> 1;          // 0..63
    int oc = nblk * 128 + row;
    int k = c * 64 + kj;
    int tap = k / ICP;
    int ic = k - tap * ICP;
    float v = (ic < IC) ? src[(oc * IC + ic) * 9 + tap] : 0.f;
    dst[h] = __float2half_rn(v);
}

__global__ void repack_all(const float* __restrict__ img, __half* __restrict__ dimg,
                           const float* __restrict__ c1w, const float* __restrict__ c2w,
                           const float* __restrict__ c3w,
                           __half* __restrict__ w1, __half* __restrict__ w2,
                           __half* __restrict__ w3)
{
    int idx = blockIdx.x * 512 + threadIdx.x;
    if (idx < IMG_ELEMS) {
        int n = idx / 16900;
        int r = idx - n * 16900;
        int ihp = r / 130;
        int iwp = r - ihp * 130;
        int ih = ihp - 1, iw = iwp - 1;
        float c0 = 0.f, c1 = 0.f, c2 = 0.f;
        if ((unsigned)ih < 128u && (unsigned)iw < 128u) {
            size_t b = (size_t)n * 3 * 16384 + ih * 128 + iw;
            c0 = img[b]; c1 = img[b + 16384]; c2 = img[b + 32768];
        }
        __half2 lo = __floats2half2_rn(c0, c1);
        __half2 hi = __floats2half2_rn(c2, 0.f);
        uint2 v;
        v.x = *(uint32_t*)&lo;
        v.y = *(uint32_t*)&hi;
        *(uint2*)(dimg + (size_t)idx * 4) = v;
    } else {
        int w = idx - IMG_ELEMS;
        if (w < W1_ELEMS) repack_w1(c1w, w1, w);
        else if (w < W1_ELEMS + W2_ELEMS)
            repack_wswz(c2w, w2, w - W1_ELEMS, 64, 64, 9);
        else if (w < W1_ELEMS + W2_ELEMS + W3_ELEMS)
            repack_wswz(c3w, w3, w - W1_ELEMS - W2_ELEMS, 128, 128, 18);
    }
}

// ---------------------------------------------------------------------------
// conv1 kernel: 256 threads, NB=64, NCH=1, 3 CTA/SM, KSTEPS=3 (K 36->48).
// Padding bytes 72..95 of each A row zeroed precisely (taps write 0..71).
// ---------------------------------------------------------------------------
__global__ void __launch_bounds__(256, 3)
conv1_kernel(const __half* __restrict__ in, const __half* __restrict__ wrep,
             const float* __restrict__ bias, __half* __restrict__ outp)
{
    constexpr int OW = 64, OH = 64;
    constexpr int NB = 64;
    constexpr uint32_t OFFA = 1024;
    constexpr uint32_t OFFB = OFFA + 16384;

    extern __shared__ char smem[];
    const uint32_t sb = smem_u32(smem);
    float* s_bias = (float*)smem;

    const int bid = blockIdx.x;
    const int n = bid >> 5;
    const int mblk = bid & 31;
    const int oh0 = mblk * 2;

    const int tid = threadIdx.x;
    const int warp = tid >> 5;
    const int lane = tid & 31;
    const int mwarp = warp >> 1;
    const int nwarp = warp & 1;

    if (tid < NB) s_bias[tid] = bias[tid];

    if (tid < 128) {
        const uint32_t rb = OFFA + (uint32_t)tid * 128;
        *(uint64_t*)(smem + swz(rb + 72)) = 0ull;
        *(uint64_t*)(smem + swz(rb + 80)) = 0ull;
        *(uint64_t*)(smem + swz(rb + 88)) = 0ull;
    }

    {
        const int am = tid >> 1;
        const int a_ohl = am >> 6;
        const int a_ow = am & 63;
        const int ihb = (oh0 + a_ohl) * 2;
        const int iwb = a_ow * 2;
#pragma unroll
        for (int i = 0; i < 5; i++) {
            int j = (tid & 1) + 2 * i;
            if (j <= 8) {
                int kh = j / 3, kw = j - kh * 3;
                const __half* src = in + (((size_t)n * 130 + ihb + kh) * 130 + iwb + kw) * 4;
                uint32_t dst = sb + OFFA + swz((uint32_t)(am * 128 + j * 8));
                asm volatile("cp.async.ca.shared.global [%0], [%1], 8;"
                             :: "r"(dst), "l"(src));
            }
        }
        const int bn = tid >> 2;
        const int bseg = (tid & 3) * 2;
#pragma unroll
        for (int i = 0; i < 2; i++) {
            const __half* src = wrep + (size_t)bn * 64 + (bseg + i) * 8;
            uint32_t dst = sb + OFFB + swz((uint32_t)(bn * 128 + (bseg + i) * 16));
            asm volatile("cp.async.cg.shared.global [%0], [%1], 16;"
                         :: "r"(dst), "l"(src));
        }
    }
    CP_COMMIT();
    CP_WAIT0();
    __syncthreads();

    float acc[2][4][4];
#pragma unroll
    for (int mt = 0; mt < 2; mt++)
#pragma unroll
        for (int nt = 0; nt < 4; nt++)
#pragma unroll
            for (int i = 0; i < 4; i++) acc[mt][nt][i] = 0.f;

#pragma unroll
    for (int ks = 0; ks < 3; ks++) {
        const uint32_t colb = ks * 32 + ((lane >> 4) << 4);
        uint32_t a[2][4], bf[2][4];
#pragma unroll
        for (int mt = 0; mt < 2; mt++) {
            const uint32_t row = mwarp * 32 + mt * 16 + (lane & 15);
            ldm_x4(a[mt], sb + OFFA + swz(row * 128 + colb));
        }
#pragma unroll
        for (int np = 0; np < 2; np++) {
            const uint32_t row = nwarp * 32 + np * 16 + (lane & 15);
            ldm_x4(bf[np], sb + OFFB + swz(row * 128 + colb));
        }
#pragma unroll
        for (int mt = 0; mt < 2; mt++)
#pragma unroll
            for (int nt = 0; nt < 4; nt++)
                mma_f16(acc[mt][nt], a[mt], bf[nt >> 1][nt & 1],
                        bf[nt >> 1][2 + (nt & 1)]);
    }
    __syncthreads();

    constexpr uint32_t ES = NB * 2 + 16;
    char* epi = smem + OFFA;
#pragma unroll
    for (int mt = 0; mt < 2; mt++) {
        const int r0 = mwarp * 32 + mt * 16 + (lane >> 2);
#pragma unroll
        for (int nt = 0; nt < 4; nt++) {
            const int c0 = nwarp * 32 + nt * 8 + (lane & 3) * 2;
            const float b0 = s_bias[c0], b1 = s_bias[c0 + 1];
            __half2 v0 = __floats2half2_rn(fmaxf(acc[mt][nt][0] + b0, 0.f),
                                           fmaxf(acc[mt][nt][1] + b1, 0.f));
            __half2 v1 = __floats2half2_rn(fmaxf(acc[mt][nt][2] + b0, 0.f),
                                           fmaxf(acc[mt][nt][3] + b1, 0.f));
            *(__half2*)(epi + r0 * ES + c0 * 2) = v0;
            *(__half2*)(epi + (r0 + 8) * ES + c0 * 2) = v1;
        }
    }
    __syncthreads();
#pragma unroll
    for (int i = 0; i < 4; i++) {
        int idx = tid + i * 256;
        int r2 = idx >> 3;
        int j = idx & 7;
        uint4 v = *(const uint4*)(epi + r2 * ES + j * 16);
        int ohl = r2 >> 6, ow = r2 & 63;
        __half* dst = outp + (((size_t)n * OH + oh0 + ohl) * OW + ow) * 64 + j * 8;
        *(uint4*)dst = v;
    }
}

// ---------------------------------------------------------------------------
// conv2/conv3: R7 mainloop, but B staged via ONE cp.async.bulk (16KB) per
// chunk from pre-swizzled global blocks; completion via 3 mbarriers
// (count=1, expect_tx 16KB, parity = (c/3)&1). A stays on cp.async.
// ---------------------------------------------------------------------------
template <int ICP, int KTOT, int OCTOT, int IH, int IW, int OH_TILE, bool FUSE_POOL>
__global__ void __launch_bounds__(256, 2)
conv_r7_kernel(const __half* __restrict__ in, const __half* __restrict__ wrep,
               const float* __restrict__ bias, void* __restrict__ outp)
{
    constexpr int OH = IH / 2, OW = IW / 2;
    constexpr int LOG_OW = (OW == 64) ? 6 : (OW == 32) ? 5 : 4;
    constexpr int NB = 128;
    constexpr int NCH = KTOT / 64;
    constexpr int CPT = ICP / 64;
    constexpr int MBLK = OH / OH_TILE;
    constexpr int NBLK = OCTOT / NB;
    constexpr int NT = 8;
    constexpr int NP = 4;
    constexpr uint32_t MB = 512;             // 3 mbarriers at 512,520,528
    constexpr uint32_t OFFA = 1024;
    constexpr uint32_t ABUF = 16384;
    constexpr uint32_t OFFB = OFFA + 3 * ABUF;
    constexpr uint32_t BBUF = NB * 128;      // 16384

    extern __shared__ char smem[];
    const uint32_t sb = smem_u32(smem);
    float* s_bias = (float*)smem;

    const int bid = blockIdx.x;
    const int n = bid / (MBLK * NBLK);
    const int r = bid - n * (MBLK * NBLK);
    const int mblk = r / NBLK;
    const int nblk = r - mblk * NBLK;
    const int oh0 = mblk * OH_TILE;

    const int tid = threadIdx.x;
    const int warp = tid >> 5;
    const int lane = tid & 31;
    const int mwarp = warp >> 1;
    const int nwarp = warp & 1;

    if (tid < NB) s_bias[tid] = bias[nblk * NB + tid];
    if (tid == 0) {
        MBARRIER_INIT(sb + MB + 0, 1);
        MBARRIER_INIT(sb + MB + 8, 1);
        MBARRIER_INIT(sb + MB + 16, 1);
    }

    const int am = tid >> 1;
    const int a_ohl = am >> LOG_OW;
    const int a_ow = am & (OW - 1);
    const __half* wbase = wrep + (size_t)nblk * NCH * 8192;

    auto issueA = [&](int c, uint32_t abase) {
        const int tap = c / CPT;
        const int ic0 = (c & (CPT - 1)) * 64;
        const int kh = tap / 3, kw = tap - kh * 3;
        const int ih = (oh0 + a_ohl) * 2 - 1 + kh;
        const int iw = a_ow * 2 - 1 + kw;
        const bool valid = ((unsigned)ih < (unsigned)IH) &&
                           ((unsigned)iw < (unsigned)IW);
        const __half* src = valid
            ? in + (((size_t)n * IH + ih) * IW + iw) * ICP + ic0 : in;
        const int sz = valid ? 16 : 0;
#pragma unroll
        for (int i = 0; i < 4; i++) {
            int u = (tid & 1) * 4 + i;
            uint32_t dst = sb + abase + swz((uint32_t)(am * 128 + u * 16));
            asm volatile("cp.async.cg.shared.global [%0], [%1], 16, %2;"
                         :: "r"(dst), "l"(src + u * 8), "r"(sz));
        }
    };
    auto issueB = [&](int c, int slot) {
        if (tid == 0) {
            MBARRIER_EXPECT_TX(sb + MB + slot * 8, BBUF);
            CP_ASYNC_BULK(sb + OFFB + (uint32_t)slot * BBUF,
                          wbase + (size_t)c * 8192, BBUF, sb + MB + slot * 8);
        }
    };

    float acc[2][NT][4];
#pragma unroll
    for (int mt = 0; mt < 2; mt++)
#pragma unroll
        for (int nt = 0; nt < NT; nt++)
#pragma unroll
            for (int i = 0; i < 4; i++) acc[mt][nt][i] = 0.f;

    auto do_mma = [&](uint32_t abase, uint32_t bbase) {
#pragma unroll
        for (int ks = 0; ks < 4; ks++) {
            const uint32_t colb = ks * 32 + ((lane >> 4) << 4);
            uint32_t a[2][4], bf[NP][4];
#pragma unroll
            for (int mt = 0; mt < 2; mt++) {
                const uint32_t row = mwarp * 32 + mt * 16 + (lane & 15);
                ldm_x4(a[mt], sb + abase + swz(row * 128 + colb));
            }
#pragma unroll
            for (int np = 0; np < NP; np++) {
                const uint32_t row = nwarp * (NB / 2) + np * 16 + (lane & 15);
                ldm_x4(bf[np], sb + bbase + swz(row * 128 + colb));
            }
#pragma unroll
            for (int mt = 0; mt < 2; mt++)
#pragma unroll
                for (int nt = 0; nt < NT; nt++)
                    mma_f16(acc[mt][nt], a[mt], bf[nt >> 1][nt & 1],
                            bf[nt >> 1][2 + (nt & 1)]);
        }
    };

    __syncthreads();   // mbarrier init visible before any wait/issue
    issueA(0, OFFA);
    CP_COMMIT();
    issueB(0, 0);
    issueA(1, OFFA + ABUF);
    CP_COMMIT();
    issueB(1, 1);

    int bi = 0;
#pragma unroll 1
    for (int c = 0; c < NCH; c++) {
        if (c + 1 < NCH) { CP_WAIT1(); } else { CP_WAIT0(); }
        MBARRIER_WAIT_PARITY(sb + MB + bi * 8, (c / 3) & 1);
        __syncthreads();
        do_mma(OFFA + (uint32_t)bi * ABUF, OFFB + (uint32_t)bi * BBUF);
        if (c + 2 < NCH) {
            int b2 = bi + 2; if (b2 >= 3) b2 -= 3;
            issueA(c + 2, OFFA + (uint32_t)b2 * ABUF);
            CP_COMMIT();
            issueB(c + 2, b2);
        }
        if (++bi == 3) bi = 0;
    }
    __syncthreads();

    if (!FUSE_POOL) {
        constexpr uint32_t ES = NB * 2 + 16;
        char* epi = smem + OFFA;
#pragma unroll
        for (int mt = 0; mt < 2; mt++) {
            const int r0 = mwarp * 32 + mt * 16 + (lane >> 2);
#pragma unroll
            for (int nt = 0; nt < NT; nt++) {
                const int c0 = nwarp * (NB / 2) + nt * 8 + (lane & 3) * 2;
                const float b0 = s_bias[c0], b1 = s_bias[c0 + 1];
                __half2 v0 = __floats2half2_rn(fmaxf(acc[mt][nt][0] + b0, 0.f),
                                               fmaxf(acc[mt][nt][1] + b1, 0.f));
                __half2 v1 = __floats2half2_rn(fmaxf(acc[mt][nt][2] + b0, 0.f),
                                               fmaxf(acc[mt][nt][3] + b1, 0.f));
                *(__half2*)(epi + r0 * ES + c0 * 2) = v0;
                *(__half2*)(epi + (r0 + 8) * ES + c0 * 2) = v1;
            }
        }
        __syncthreads();
        constexpr int ROWB = NB / 8;
        __half* outh = (__half*)outp;
#pragma unroll
        for (int i = 0; i < 8; i++) {
            int idx = tid + i * 256;
            int r2 = idx / ROWB;
            int j = idx & (ROWB - 1);
            uint4 v = *(const uint4*)(epi + r2 * ES + j * 16);
            int ohl = r2 >> LOG_OW, ow = r2 & (OW - 1);
            __half* dst = outh + (((size_t)n * OH + oh0 + ohl) * OW + ow) * OCTOT
                        + nblk * NB + j * 8;
            *(uint4*)dst = v;
        }
    } else {
        float* s_red = (float*)(smem + OFFA);
#pragma unroll
        for (int nt = 0; nt < NT; nt++) {
            const int c0 = nwarp * (NB / 2) + nt * 8 + (lane & 3) * 2;
            const float b0 = s_bias[c0], b1 = s_bias[c0 + 1];
            float s0 = 0.f, s1 = 0.f;
#pragma unroll
            for (int mt = 0; mt < 2; mt++) {
                s0 += fmaxf(acc[mt][nt][0] + b0, 0.f) + fmaxf(acc[mt][nt][2] + b0, 0.f);
                s1 += fmaxf(acc[mt][nt][1] + b1, 0.f) + fmaxf(acc[mt][nt][3] + b1, 0.f);
            }
#pragma unroll
            for (int off = 16; off >= 4; off >>= 1) {
                s0 += __shfl_xor_sync(0xffffffffu, s0, off);
                s1 += __shfl_xor_sync(0xffffffffu, s1, off);
            }
            if ((lane >> 2) == 0) {
                s_red[c0 * 4 + mwarp] = s0;
                s_red[(c0 + 1) * 4 + mwarp] = s1;
            }
        }
        __syncthreads();
        if (tid < NB) {
            float s = s_red[tid * 4] + s_red[tid * 4 + 1]
                    + s_red[tid * 4 + 2] + s_red[tid * 4 + 3];
            ((float*)outp)[((size_t)n * MBLK + mblk) * 256 + nblk * NB + tid] = s;
        }
    }
}

// ---------------------------------------------------------------------------
// Fused per-sample MLP chain — 512 threads, float4 split-K (R16-proven).
// ---------------------------------------------------------------------------
__global__ void __launch_bounds__(512)
mlp_chain_kernel(const float* __restrict__ vpart, const float* __restrict__ prop,
                 const int* __restrict__ task_ids,
                 const float* __restrict__ p1_w, const float* __restrict__ p1_b,
                 const float* __restrict__ p2_w, const float* __restrict__ p2_b,
                 const float* __restrict__ f1_w, const float* __restrict__ f1_b,
                 const float* __restrict__ f2_w, const float* __restrict__ f2_b,
                 const float* __restrict__ task_emb,
                 const float* __restrict__ g_w, const float* __restrict__ g_b,
                 const float* __restrict__ h1_w, const float* __restrict__ h1_b,
                 const float* __restrict__ h2_w, const float* __restrict__ h2_b,
                 const float* __restrict__ h3_w, const float* __restrict__ h3_b,
                 float* __restrict__ out)
{
    const int n = blockIdx.x;
    const int tid = threadIdx.x;

    __shared__ float sA[320];
    __shared__ float sB[256];
    __shared__ float sP[2048];
    __shared__ float sx[7];
    __shared__ float sh[64];

    if (tid < 256)
        sA[tid] = (vpart[((size_t)n * 2 + 0) * 256 + tid] +
                   vpart[((size_t)n * 2 + 1) * 256 + tid]) * (1.f / 256.f);
    if (tid < 7) sx[tid] = prop[n * 7 + tid];
    const int t = task_ids[n];
    __syncthreads();

    if (tid < 64) {
        float a = p1_b[tid];
#pragma unroll
        for (int i = 0; i < 7; i++) a += sx[i] * p1_w[i * 64 + tid];
        sh[tid] = fmaxf(a, 0.f);
    }
    __syncthreads();

#define LAYER_COMPUTE(W, SIN, OUT, OG, KPG)                                    \
    {                                                                          \
        const int og = tid & (OG - 1);                                         \
        const int kg = tid / OG;                                               \
        const int k0 = kg * KPG;                                               \
        float4 acc = make_float4(0.f, 0.f, 0.f, 0.f);                          \
        _Pragma("unroll 4")                                                    \
        for (int i = 0; i < KPG; i++) {                                        \
            const float a = SIN[k0 + i];                                       \
            const float4 w4 = *(const float4*)&W[(size_t)(k0 + i) * OUT + og * 4]; \
            acc.x += a * w4.x; acc.y += a * w4.y;                              \
            acc.z += a * w4.z; acc.w += a * w4.w;                              \
        }                                                                      \
        *(float4*)&sP[tid * 4] = acc;                                          \
    }
#define LAYER_REDUCE(BIASEXPR, SOUT, OUT, OG, GK, RELU)                        \
    if (tid < OUT) {                                                           \
        float s = (BIASEXPR);                                                  \
        const int base = ((tid >> 2) << 2) + (tid & 3);                        \
        _Pragma("unroll")                                                      \
        for (int kg = 0; kg < GK; kg++) s += sP[kg * (OG * 4) + base];         \
        SOUT[tid] = RELU ? fmaxf(s, 0.f) : s;                                  \
    }

    LAYER_COMPUTE(p2_w, sh, 64, 16, 2);
    __syncthreads();
    if (tid < 64) {
        float s = p2_b[tid];
        const int base = ((tid >> 2) << 2) + (tid & 3);
#pragma unroll
        for (int kg = 0; kg < 32; kg++) s += sP[kg * 64 + base];
        sA[256 + tid] = s;
    }
    __syncthreads();

    LAYER_COMPUTE(f1_w, sA, 256, 64, 40);
    __syncthreads();
    LAYER_REDUCE(f1_b[tid], sB, 256, 64, 8, true);
    __syncthreads();

    LAYER_COMPUTE(f2_w, sB, 256, 64, 32);
    __syncthreads();
    LAYER_REDUCE(f2_b[tid], sA, 256, 64, 8, true);
    if (tid >= 256 && tid < 288) sA[tid] = task_emb[t * 32 + (tid - 256)];
    __syncthreads();

    LAYER_COMPUTE(g_w, sA, 256, 64, 36);
    __syncthreads();
    LAYER_REDUCE(g_b[tid], sB, 256, 64, 8, true);
    __syncthreads();

    {
        const float* w1 = h1_w + (size_t)t * ENC_DIM * HEAD_HID;
        LAYER_COMPUTE(w1, sB, 128, 32, 16);
    }
    __syncthreads();
    LAYER_REDUCE(h1_b[t * 128 + tid], sA, 128, 32, 16, true);
    __syncthreads();

    {
        const float* w2 = h2_w + (size_t)t * HEAD_HID * HEAD_HID;
        LAYER_COMPUTE(w2, sA, 128, 32, 8);
    }
    __syncthreads();
    LAYER_REDUCE(h2_b[t * 128 + tid], sB, 128, 32, 16, true);
    __syncthreads();

    if (tid < 128) {
        const float* w3 = h3_w + (size_t)t * HEAD_HID * 4;
        const int o = tid >> 5;
        const int l = tid & 31;
        float a = 0.f;
#pragma unroll
        for (int j = 0; j < 4; j++) a += sB[l + j * 32] * w3[(l + j * 32) * 4 + o];
#pragma unroll
        for (int d = 16; d > 0; d >>= 1) a += __shfl_xor_sync(0xffffffffu, a, d);
        if (l == 0) out[n * 4 + o] = a + h3_b[t * 4 + o];
    }
#undef LAYER_COMPUTE
#undef LAYER_REDUCE
}

// ---------------------------------------------------------------------------
extern "C" void kernel_launch(void* const* d_in, const int* in_sizes, int n_in,
                              void* d_out, int out_size)
{
    const float* images = (const float*)d_in[0];
    const float* prop   = (const float*)d_in[1];
    const int*   tids   = (const int*)d_in[2];
    const float* c1_w = (const float*)d_in[3];
    const float* c1_b = (const float*)d_in[4];
    const float* c2_w = (const float*)d_in[5];
    const float* c2_b = (const float*)d_in[6];
    const float* c3_w = (const float*)d_in[7];
    const float* c3_b = (const float*)d_in[8];
    const float* p1_w = (const float*)d_in[9];
    const float* p1_b = (const float*)d_in[10];
    const float* p2_w = (const float*)d_in[11];
    const float* p2_b = (const float*)d_in[12];
    const float* f1_w = (const float*)d_in[13];
    const float* f1_b = (const float*)d_in[14];
    const float* f2_w = (const float*)d_in[15];
    const float* f2_b = (const float*)d_in[16];
    const float* temb = (const float*)d_in[17];
    const float* g_w  = (const float*)d_in[18];
    const float* g_b  = (const float*)d_in[19];
    const float* h1_w = (const float*)d_in[20];
    const float* h1_b = (const float*)d_in[21];
    const float* h2_w = (const float*)d_in[22];
    const float* h2_b = (const float*)d_in[23];
    const float* h3_w = (const float*)d_in[24];
    const float* h3_b = (const float*)d_in[25];
    float* out = (float*)d_out;

    __half *imgT, *act1, *act2, *w1r, *w2r, *w3r;
    float* vpart;
    cudaGetSymbolAddress((void**)&imgT, g_imgT);
    cudaGetSymbolAddress((void**)&act1, g_act1);
    cudaGetSymbolAddress((void**)&act2, g_act2);
    cudaGetSymbolAddress((void**)&w1r, g_w1rep);
    cudaGetSymbolAddress((void**)&w2r, g_w2rep);
    cudaGetSymbolAddress((void**)&w3r, g_w3rep);
    cudaGetSymbolAddress((void**)&vpart, g_vpart);

    // fused repack (img + all conv weights; w2/w3 pre-swizzled blocks)
    repack_all<<<(IMG_ELEMS + W1_ELEMS + W2_ELEMS + W3_ELEMS + 511) / 512, 512>>>(
        images, imgT, c1_w, c2_w, c3_w, w1r, w2r, w3r);

    // conv1: imgT -> act1 [256,64,64,64] NHWC half. 256 thr, NB=64, 3 CTA/SM
    {
        constexpr int SM = 1024 + 16384 + 8192;
        cudaFuncSetAttribute(conv1_kernel,
                             cudaFuncAttributeMaxDynamicSharedMemorySize, SM);
        conv1_kernel<<<BATCH * 32, 256, SM>>>(imgT, w1r, c1_b, act1);
    }
    // conv2: act1 -> act2 [256,32,32,128]. NB=128, 2 CTA/SM, bulk-B
    {
        constexpr int SM = 50176 + 3 * (128 * 128);   // 99328
        auto k = conv_r7_kernel<64, 576, 128, 64, 64, 4, false>;
        cudaFuncSetAttribute(k, cudaFuncAttributeMaxDynamicSharedMemorySize, SM);
        k<<<BATCH * 8, 256, SM>>>(act1, w2r, c2_b, act2);
    }
    // conv3 + pool partials -> vpart. bulk-B
    {
        constexpr int SM = 50176 + 3 * (128 * 128);
        auto k = conv_r7_kernel<128, 1152, 256, 32, 32, 8, true>;
        cudaFuncSetAttribute(k, cudaFuncAttributeMaxDynamicSharedMemorySize, SM);
        k<<<BATCH * 2 * 2, 256, SM>>>(act2, w3r, c3_b, vpart);
    }

    mlp_chain_kernel<<<BATCH, 512>>>(
        vpart, prop, tids,
        p1_w, p1_b, p2_w, p2_b,
        f1_w, f1_b, f2_w, f2_b,
        temb, g_w, g_b,
        h1_w, h1_b, h2_w, h2_b, h3_w, h3_b,
        out);
}